// round 6
// baseline (speedup 1.0000x reference)
#include <cuda_runtime.h>
#include <cuda_fp16.h>
#include <cstdint>

// Problem dims
#define NB 256
#define NS 256
#define ND 64
#define NH 1024
#define NG 4096
#define NT 32
#define BHE (NB*NH)

// GEMM tiling
#define BM 128
#define BN 64
#define BK 32
#define AP 40                     // padded K-stride (halves): conflict-free ldmatrix
#define A_ST (BM*AP)              // 5120 halves
#define B_ST (BN*AP)              // 2560 halves
#define STAGE_H (A_ST + B_ST)     // 7680 halves = 15360 B
#define NSTAGE 4
#define SMEM_BYTES (NSTAGE*STAGE_H*2)   // 61440 B

// ---------------- device scratch (static: no allocs allowed) ----------------
__device__ __align__(128) __half g_Xh [NS*NB*ND];          // X time-major fp16
__device__ __align__(128) __half g_W0 [(size_t)NG*1088];   // [enc_Wih0 | enc_Whh0]
__device__ __align__(128) __half g_W1 [(size_t)NG*2048];   // [enc_Wih1 | enc_Whh1]
__device__ __align__(128) __half g_DW0[(size_t)NG*1024];   // dec_Whh0
__device__ __align__(128) __half g_DW1[(size_t)NG*2048];   // [dec_Wih1 | dec_Whh1]
__device__ __align__(128) __half g_h0 [2*BHE];             // layer-0 h ping-pong
__device__ __align__(128) __half g_h1 [2*BHE];             // layer-1 h ping-pong
__device__ __align__(128) float  g_c0 [BHE];
__device__ __align__(128) float  g_c1 [BHE];
__device__ __align__(128) float  g_h1f[BHE];               // fp32 h1 for fc
__device__ __align__(128) float  g_pred[NB];

// ---------------- PTX helpers ----------------
__device__ __forceinline__ uint32_t smem_u32(const void* p){
    return (uint32_t)__cvta_generic_to_shared(p);
}
__device__ __forceinline__ void cp_async16(uint32_t s, const void* g){
    asm volatile("cp.async.cg.shared.global [%0], [%1], 16;\n" :: "r"(s), "l"(g));
}
__device__ __forceinline__ void cp_commit(){
    asm volatile("cp.async.commit_group;\n" ::: "memory");
}
template<int N> __device__ __forceinline__ void cp_wait(){
    asm volatile("cp.async.wait_group %0;\n" :: "n"(N) : "memory");
}
__device__ __forceinline__ void ldsm_x4(uint32_t&r0,uint32_t&r1,uint32_t&r2,uint32_t&r3,uint32_t a){
    asm volatile("ldmatrix.sync.aligned.m8n8.x4.shared.b16 {%0,%1,%2,%3},[%4];\n"
        : "=r"(r0),"=r"(r1),"=r"(r2),"=r"(r3) : "r"(a));
}
__device__ __forceinline__ void mma16816(float* c,
    uint32_t a0,uint32_t a1,uint32_t a2,uint32_t a3,uint32_t b0,uint32_t b1){
    asm volatile("mma.sync.aligned.m16n8k16.row.col.f32.f16.f16.f32 "
        "{%0,%1,%2,%3},{%4,%5,%6,%7},{%8,%9},{%0,%1,%2,%3};\n"
        : "+f"(c[0]),"+f"(c[1]),"+f"(c[2]),"+f"(c[3])
        : "r"(a0),"r"(a1),"r"(a2),"r"(a3),"r"(b0),"r"(b1));
}
__device__ __forceinline__ float sigf(float x){ return 1.f/(1.f + __expf(-x)); }
__device__ __forceinline__ float tanhf2(float x){ return 2.f/(1.f + __expf(-2.f*x)) - 1.f; }

// ---------------- stage loader ----------------
// A tile: [BM x BK] halves from two sources split at K0 (K0 multiple of BK or 0)
// B tile: [BN x BK], gate-gathered: smem row r -> W row (r/16)*1024 + u0 + (r%16)
__device__ __forceinline__ void load_stage(
    __half* sm, int s, int tid, int m_base, int u0,
    const __half* A0, int lda0, int K0,
    const __half* A1, int lda1,
    const __half* W, int Ktot)
{
    __half* sA = sm + (s & 3)*STAGE_H;
    __half* sB = sA + A_ST;
    int kb = s*BK;
    const __half* Asrc; int lda; int kk;
    if (kb < K0){ Asrc = A0; lda = lda0; kk = kb; }
    else        { Asrc = A1; lda = lda1; kk = kb - K0; }
#pragma unroll
    for (int i = 0; i < 2; i++){
        int c   = tid + i*256;
        int row = c >> 2, cg = (c & 3)*8;
        cp_async16(smem_u32(sA + row*AP + cg),
                   Asrc + (size_t)(m_base + row)*lda + (kk + cg));
    }
    {
        int row = tid >> 2, cg = (tid & 3)*8;
        int wrow = ((row >> 4) << 10) + u0 + (row & 15);   // gate-gather
        cp_async16(smem_u32(sB + row*AP + cg),
                   W + (size_t)wrow*Ktot + (kb + cg));
    }
}

// ---------------- fused LSTM step kernel ----------------
// gates = [A0|A1] @ W^T (+ bias) (+ p*r1w rank-1)  -> cell -> h(fp16[,fp32]), c(fp32)
__global__ void __launch_bounds__(256,1) lstm_step(
    const __half* __restrict__ A0, int lda0, int K0,
    const __half* __restrict__ A1, int lda1, int K1,
    const __half* __restrict__ W,
    const float*  __restrict__ bias,
    const float*  __restrict__ r1w,   // [4096] or null
    const float*  __restrict__ r1x,   // [NB]  or null
    float*  __restrict__ cbuf,        // [NB,NH] in/out
    __half* __restrict__ dh,          // [NB,NH] fp16 h out
    float*  __restrict__ dhf)         // optional fp32 h out
{
    extern __shared__ __half sm[];
    const int tid  = threadIdx.x;
    const int warp = tid >> 5;
    const int l    = tid & 31;
    const int wm   = warp & 3;        // 4 M-warps
    const int wn   = warp >> 2;       // 2 N-warps
    const int u0     = blockIdx.x * 16;     // 16 units per CTA (64 gate-cols)
    const int m_base = blockIdx.y * BM;

    const int Ktot    = K0 + K1;
    const int nstages = Ktot / BK;

    float acc[2][4][4];
#pragma unroll
    for (int i=0;i<2;i++)
#pragma unroll
        for (int j=0;j<4;j++)
#pragma unroll
            for (int k=0;k<4;k++) acc[i][j][k] = 0.f;

    for (int s = 0; s < 3; s++){           // prologue (nstages >= 32 always)
        load_stage(sm, s, tid, m_base, u0, A0, lda0, K0, A1, lda1, W, Ktot);
        cp_commit();
    }

    for (int s = 0; s < nstages; s++){
        cp_wait<2>();
        __syncthreads();
        if (s + 3 < nstages)
            load_stage(sm, s+3, tid, m_base, u0, A0, lda0, K0, A1, lda1, W, Ktot);
        cp_commit();

        __half* sA = sm + (s & 3)*STAGE_H;
        __half* sB = sA + A_ST;
#pragma unroll
        for (int kk = 0; kk < BK; kk += 16){
            uint32_t a[2][4], b[4][2];
#pragma unroll
            for (int fm = 0; fm < 2; fm++){
                int row = wm*32 + fm*16 + (l & 15);
                uint32_t ad = smem_u32(sA + row*AP + kk + ((l & 16) >> 1));
                ldsm_x4(a[fm][0], a[fm][1], a[fm][2], a[fm][3], ad);
            }
#pragma unroll
            for (int nh = 0; nh < 2; nh++){
                int row = wn*32 + nh*16 + (l & 7) + ((l >> 4) & 1)*8;
                uint32_t ad = smem_u32(sB + row*AP + kk + (l & 8));
                ldsm_x4(b[2*nh][0], b[2*nh][1], b[2*nh+1][0], b[2*nh+1][1], ad);
            }
#pragma unroll
            for (int fm = 0; fm < 2; fm++)
#pragma unroll
                for (int fn = 0; fn < 4; fn++)
                    mma16816(acc[fm][fn], a[fm][0],a[fm][1],a[fm][2],a[fm][3],
                             b[fn][0], b[fn][1]);
        }
    }

    // ---------------- epilogue: gates -> SMEM -> cell ----------------
    cp_wait<0>();
    __syncthreads();
    float* sg = reinterpret_cast<float*>(sm);    // [128][65] floats (33 KB)
    {
        const int rb = wm*32, cb = wn*32;
#pragma unroll
        for (int fm = 0; fm < 2; fm++)
#pragma unroll
            for (int fn = 0; fn < 4; fn++){
                int r = rb + fm*16 + (l >> 2);
                int c = cb + fn*8  + (l & 3)*2;
                sg[r*65 + c]        = acc[fm][fn][0];
                sg[r*65 + c + 1]    = acc[fm][fn][1];
                sg[(r+8)*65 + c]    = acc[fm][fn][2];
                sg[(r+8)*65 + c+1]  = acc[fm][fn][3];
            }
    }
    __syncthreads();
    {
        const bool has_r1 = (r1w != nullptr);
        int m  = tid >> 1;
        int ub = (tid & 1)*8;
        int mg = m_base + m;
        float p = has_r1 ? r1x[mg] : 0.f;
#pragma unroll
        for (int j = 0; j < 8; j++){
            int uu = ub + j;
            int ug = u0 + uu;
            float gi = sg[m*65 + uu]      + bias[ug];
            float gf = sg[m*65 + 16 + uu] + bias[NH + ug];
            float gg = sg[m*65 + 32 + uu] + bias[2*NH + ug];
            float go = sg[m*65 + 48 + uu] + bias[3*NH + ug];
            if (has_r1){
                gi += p*r1w[ug];        gf += p*r1w[NH + ug];
                gg += p*r1w[2*NH + ug]; go += p*r1w[3*NH + ug];
            }
            int ci = mg*NH + ug;
            float cn = sigf(gf)*cbuf[ci] + sigf(gi)*tanhf2(gg);
            float hv = sigf(go)*tanhf2(cn);
            cbuf[ci] = cn;
            dh[(size_t)mg*NH + ug] = __float2half(hv);
            if (dhf) dhf[ci] = hv;
        }
    }
}

// ---------------- small kernels ----------------
__global__ void conv_x(const float* __restrict__ X, __half* __restrict__ Xh){
    int i = blockIdx.x*256 + threadIdx.x;          // [s][b][d] linear
    if (i < NS*NB*ND){
        int d = i & 63, b = (i >> 6) & 255, s = i >> 14;
        Xh[i] = __float2half(X[((size_t)b << 14) + (s << 6) + d]);
    }
}

// dst [4096][Ka+Kb] = [A | Bw] fp32->fp16
__global__ void conv_w(const float* __restrict__ A, int Ka,
                       const float* __restrict__ Bw, int Kb,
                       __half* __restrict__ dst, int total){
    int i = blockIdx.x*256 + threadIdx.x;
    if (i < total){
        int Kt = Ka + Kb;
        int k = i % Kt, n = i / Kt;
        float v = (k < Ka) ? A[(size_t)n*Ka + k] : Bw[(size_t)n*Kb + (k - Ka)];
        dst[i] = __float2half(v);
    }
}

__global__ void fc_kernel(const float* __restrict__ h1, const float* __restrict__ fcW,
                          const float* __restrict__ fcb, float* __restrict__ pred,
                          float* __restrict__ out, int t){
    __shared__ float red[4];
    int b = blockIdx.x, tid = threadIdx.x;
    float s = 0.f;
    for (int u = tid; u < NH; u += 128) s += h1[b*NH + u]*fcW[u];
#pragma unroll
    for (int o = 16; o; o >>= 1) s += __shfl_xor_sync(0xFFFFFFFFu, s, o);
    if ((tid & 31) == 0) red[tid >> 5] = s;
    __syncthreads();
    if (tid == 0){
        float v = red[0] + red[1] + red[2] + red[3] + fcb[0];
        pred[b] = v;
        out[b*NT + t] = v;
    }
}

// ---------------- host ----------------
extern "C" void kernel_launch(void* const* d_in, const int* in_sizes, int n_in,
                              void* d_out, int out_size){
    const float* X    = (const float*)d_in[0];
    const float* eW0i = (const float*)d_in[1];
    const float* eW0h = (const float*)d_in[2];
    const float* eb0  = (const float*)d_in[3];
    const float* eW1i = (const float*)d_in[4];
    const float* eW1h = (const float*)d_in[5];
    const float* eb1  = (const float*)d_in[6];
    const float* dW0i = (const float*)d_in[7];
    const float* dW0h = (const float*)d_in[8];
    const float* db0  = (const float*)d_in[9];
    const float* dW1i = (const float*)d_in[10];
    const float* dW1h = (const float*)d_in[11];
    const float* db1  = (const float*)d_in[12];
    const float* fcW  = (const float*)d_in[13];
    const float* fcb  = (const float*)d_in[14];
    float* out = (float*)d_out;

    __half *Xh, *W0, *W1, *DW0, *DW1, *h0, *h1;
    float *c0, *c1, *h1f, *pred;
    cudaGetSymbolAddress((void**)&Xh,  g_Xh);
    cudaGetSymbolAddress((void**)&W0,  g_W0);
    cudaGetSymbolAddress((void**)&W1,  g_W1);
    cudaGetSymbolAddress((void**)&DW0, g_DW0);
    cudaGetSymbolAddress((void**)&DW1, g_DW1);
    cudaGetSymbolAddress((void**)&h0,  g_h0);
    cudaGetSymbolAddress((void**)&h1,  g_h1);
    cudaGetSymbolAddress((void**)&c0,  g_c0);
    cudaGetSymbolAddress((void**)&c1,  g_c1);
    cudaGetSymbolAddress((void**)&h1f, g_h1f);
    cudaGetSymbolAddress((void**)&pred, g_pred);

    cudaFuncSetAttribute(lstm_step, cudaFuncAttributeMaxDynamicSharedMemorySize, SMEM_BYTES);

    // initial states: t=0 reads ping-pong buffer 1
    cudaMemsetAsync(h0 + BHE, 0, BHE*sizeof(__half));
    cudaMemsetAsync(h1 + BHE, 0, BHE*sizeof(__half));
    cudaMemsetAsync(c0, 0, BHE*sizeof(float));
    cudaMemsetAsync(c1, 0, BHE*sizeof(float));
    cudaMemsetAsync(pred, 0, NB*sizeof(float));

    conv_x<<<(NS*NB*ND + 255)/256, 256>>>(X, Xh);
    {
        int t0 = NG*1088; conv_w<<<(t0+255)/256,256>>>(eW0i,   64, eW0h, 1024, W0,  t0);
        int t1 = NG*2048; conv_w<<<(t1+255)/256,256>>>(eW1i, 1024, eW1h, 1024, W1,  t1);
        int t2 = NG*1024; conv_w<<<(t2+255)/256,256>>>(dW0h, 1024, dW0h,    0, DW0, t2);
        int t3 = NG*2048; conv_w<<<(t3+255)/256,256>>>(dW1i, 1024, dW1h, 1024, DW1, t3);
    }

    dim3 grid(NG/BN, NB/BM);   // 64 x 2

    // encoder: interleave layer0 / layer1 per timestep
    for (int t = 0; t < NS; t++){
        int wr = t & 1, rd = wr ^ 1;
        lstm_step<<<grid, 256, SMEM_BYTES>>>(
            Xh + (size_t)t*NB*ND, ND, ND,
            h0 + rd*BHE, NH, NH,
            W0, eb0, nullptr, nullptr, c0,
            h0 + wr*BHE, nullptr);
        lstm_step<<<grid, 256, SMEM_BYTES>>>(
            h0 + wr*BHE, NH, NH,
            h1 + rd*BHE, NH, NH,
            W1, eb1, nullptr, nullptr, c1,
            h1 + wr*BHE, nullptr);
    }

    // decoder: encoder ended on parity 1, so s=0 reads buffer 1 (rd = 1). OK.
    for (int s = 0; s < NT; s++){
        int wr = s & 1, rd = wr ^ 1;
        lstm_step<<<grid, 256, SMEM_BYTES>>>(
            nullptr, 0, 0,
            h0 + rd*BHE, NH, NH,
            DW0, db0, dW0i, pred, c0,
            h0 + wr*BHE, nullptr);
        lstm_step<<<grid, 256, SMEM_BYTES>>>(
            h0 + wr*BHE, NH, NH,
            h1 + rd*BHE, NH, NH,
            DW1, db1, nullptr, nullptr, c1,
            h1 + wr*BHE, h1f);
        fc_kernel<<<NB, 128>>>(h1f, fcW, fcb, pred, out, s);
    }
}